// round 4
// baseline (speedup 1.0000x reference)
#include <cuda_runtime.h>
#include <cuda_bf16.h>

#define BATCH 2
#define CH 512
#define FH 50
#define FW 75
#define HW (FH * FW)          // 3750
#define PH 8
#define PW 8
#define OUT_PER_ROI (CH * 7 * 7)          // 25088 floats
#define SMEM_BYTES (OUT_PER_ROI * 4)      // 100352 bytes
#define SPATIAL_SCALE (1.0f / 16.0f)

// NHWC scratch: 2 * 3750 * 512 floats = 15.36 MB (fits L2)
__device__ float g_feat_hwc[BATCH * HW * CH];

// ---------------------------------------------------------------------------
// Kernel 1: NCHW -> NHWC transpose.
// ---------------------------------------------------------------------------
__global__ void transpose_nchw_nhwc(const float* __restrict__ in) {
    __shared__ float tile[32][33];
    const int b   = blockIdx.z;
    const int hw0 = blockIdx.x * 32;
    const int c0  = blockIdx.y * 32;

    const float* src = in + (size_t)b * CH * HW;
    float*       dst = g_feat_hwc + (size_t)b * HW * CH;

    #pragma unroll
    for (int t = 0; t < 32; t += 8) {
        int c  = c0 + threadIdx.y + t;
        int hw = hw0 + threadIdx.x;
        if (hw < HW)
            tile[threadIdx.y + t][threadIdx.x] = src[(size_t)c * HW + hw];
    }
    __syncthreads();
    #pragma unroll
    for (int t = 0; t < 32; t += 8) {
        int hw = hw0 + threadIdx.y + t;
        int c  = c0 + threadIdx.x;
        if (hw < HW)
            dst[(size_t)hw * CH + c] = tile[threadIdx.x][threadIdx.y + t];
    }
}

// ---------------------------------------------------------------------------
// Geometry in smem (uniform for whole CTA)
// ---------------------------------------------------------------------------
__shared__ int   s_hs[PH], s_ws[PW];
__shared__ float s_hr[PH], s_wr[PW];
__shared__ int   s_hv[PH], s_wv[PW];
__shared__ int   s_b;

// Load one feature row, producing 8 w-interpolated values.
// Column-dedup: ws is nondecreasing, so consecutive j share corner columns.
// All branches depend on smem values -> uniform, no divergence.
__device__ __forceinline__ void load_row_winterp(const float* __restrict__ rowp,
                                                 float (&w)[PW]) {
    int   cl = -1000000;   // column index of cached left value
    float va = 0.0f, vb = 0.0f;  // values at columns cl, cl+1
    #pragma unroll
    for (int j = 0; j < PW; j++) {
        const int   wsj = s_ws[j];
        const float wrj = s_wr[j];
        if (wsj == cl) {
            // reuse both
        } else if (wsj == cl + 1) {
            va = vb;
            vb = __ldg(rowp + (size_t)(wsj + 1) * CH);
            cl = wsj;
        } else {
            va = __ldg(rowp + (size_t)wsj * CH);
            vb = __ldg(rowp + (size_t)(wsj + 1) * CH);
            cl = wsj;
        }
        w[j] = fmaf(vb - va, wrj, va);
    }
}

// ---------------------------------------------------------------------------
// Kernel 2: one CTA per roi, 512 threads = one channel each.
// Separable bilinear with row/column reuse, fused 2x2 avg pool,
// smem-staged coalesced output.
// ---------------------------------------------------------------------------
__global__ __launch_bounds__(CH, 2)
void roi_plus_avg_kernel(const float* __restrict__ rois,
                         float* __restrict__ out) {
    extern __shared__ float s_out[];   // OUT_PER_ROI floats

    const int n = blockIdx.x;
    const int c = threadIdx.x;

    if (threadIdx.x < PH) {
        const int i = threadIdx.x;
        const float x1 = rois[n * 5 + 1] * SPATIAL_SCALE;
        const float y1 = rois[n * 5 + 2] * SPATIAL_SCALE;
        const float x2 = rois[n * 5 + 3] * SPATIAL_SCALE;
        const float y2 = rois[n * 5 + 4] * SPATIAL_SCALE;
        const float roi_w = fmaxf(x2 - x1 + 1.0f, 0.0f);
        const float roi_h = fmaxf(y2 - y1 + 1.0f, 0.0f);
        const float bin_h = roi_h * (1.0f / (PH - 1));
        const float bin_w = roi_w * (1.0f / (PW - 1));

        const float hh = y1 + (float)i * bin_h;
        const float ww = x1 + (float)i * bin_w;

        s_hv[i] = (hh >= 0.0f) && (hh < (float)FH);
        s_wv[i] = (ww >= 0.0f) && (ww < (float)FW);

        int hs = (int)floorf(hh);
        int ws = (int)floorf(ww);
        hs = min(max(hs, 0), FH - 2);
        ws = min(max(ws, 0), FW - 2);
        s_hs[i] = hs;
        s_ws[i] = ws;
        s_hr[i] = hh - (float)hs;
        s_wr[i] = ww - (float)ws;

        if (i == 0) s_b = (int)rois[n * 5 + 0];
    }
    __syncthreads();

    const float* fb = g_feat_hwc + (size_t)s_b * HW * CH + c;

    float wtop[PW];   // w-interp values at feature row 'prevTop'
    float wbot[PW];   // w-interp values at feature row 'prevBot'
    float prev[PW];   // previous sample row (post h-interp, masked)
    int prevTop = -1000000, prevBot = -1000000;

    for (int i = 0; i < PH; i++) {
        const int top = s_hs[i];
        const int bot = top + 1;

        if (top == prevTop) {
            // same row pair as last i: wtop/wbot already valid
        } else if (top == prevBot) {
            #pragma unroll
            for (int j = 0; j < PW; j++) wtop[j] = wbot[j];
            load_row_winterp(fb + (size_t)bot * FW * CH, wbot);
        } else {
            load_row_winterp(fb + (size_t)top * FW * CH, wtop);
            load_row_winterp(fb + (size_t)bot * FW * CH, wbot);
        }
        prevTop = top;
        prevBot = bot;

        const float hr = s_hr[i];
        const bool  hv = (s_hv[i] != 0);

        float cur[PW];
        #pragma unroll
        for (int j = 0; j < PW; j++) {
            float v = fmaf(wbot[j] - wtop[j], hr, wtop[j]);
            cur[j] = (hv && s_wv[j]) ? v : 0.0f;
        }

        if (i > 0) {
            float* o = s_out + c * 49 + (i - 1) * 7;  // stride 49 -> conflict-free
            #pragma unroll
            for (int j = 0; j < 7; j++)
                o[j] = 0.25f * (prev[j] + prev[j + 1] + cur[j] + cur[j + 1]);
        }
        #pragma unroll
        for (int j = 0; j < PW; j++) prev[j] = cur[j];
    }

    __syncthreads();

    // Cooperative fully-coalesced copy-out: 25088 floats = 6272 float4
    float4*       dst4 = (float4*)(out + (size_t)n * OUT_PER_ROI);
    const float4* src4 = (const float4*)s_out;
    #pragma unroll 4
    for (int idx = threadIdx.x; idx < OUT_PER_ROI / 4; idx += CH)
        dst4[idx] = src4[idx];
}

// ---------------------------------------------------------------------------
extern "C" void kernel_launch(void* const* d_in, const int* in_sizes, int n_in,
                              void* d_out, int out_size) {
    const float* features = (const float*)d_in[0];
    const float* rois     = (const float*)d_in[1];
    float*       out      = (float*)d_out;
    const int n_rois = in_sizes[1] / 5;

    cudaFuncSetAttribute(roi_plus_avg_kernel,
                         cudaFuncAttributeMaxDynamicSharedMemorySize,
                         SMEM_BYTES);

    dim3 tgrid((HW + 31) / 32, CH / 32, BATCH);
    dim3 tblk(32, 8);
    transpose_nchw_nhwc<<<tgrid, tblk>>>(features);

    roi_plus_avg_kernel<<<n_rois, CH, SMEM_BYTES>>>(rois, out);
}

// round 5
// speedup vs baseline: 1.2708x; 1.2708x over previous
#include <cuda_runtime.h>
#include <cuda_bf16.h>

#define BATCH 2
#define CH 512
#define FH 50
#define FW 75
#define HW (FH * FW)          // 3750
#define QH (FH - 1)           // 49
#define QW (FW - 1)           // 74
#define PH 8
#define PW 8
#define OUT_PER_ROI (CH * 7 * 7)          // 25088 floats
#define SMEM_BYTES (OUT_PER_ROI * 4)      // 100352 bytes
#define SPATIAL_SCALE (1.0f / 16.0f)

// NHWC scratch: 15.36 MB
__device__ float g_feat_hwc[BATCH * HW * CH];
// Quad-corner layout: quad[b][h][w][c] = {f(h,w), f(h,w+1), f(h+1,w), f(h+1,w+1)}
// 2 * 49 * 74 * 512 * 16B = 59.4 MB
__device__ float4 g_quad[BATCH * QH * QW * CH];

// ---------------------------------------------------------------------------
// Kernel 1: NCHW -> NHWC transpose.
// ---------------------------------------------------------------------------
__global__ void transpose_nchw_nhwc(const float* __restrict__ in) {
    __shared__ float tile[32][33];
    const int b   = blockIdx.z;
    const int hw0 = blockIdx.x * 32;
    const int c0  = blockIdx.y * 32;

    const float* src = in + (size_t)b * CH * HW;
    float*       dst = g_feat_hwc + (size_t)b * HW * CH;

    #pragma unroll
    for (int t = 0; t < 32; t += 8) {
        int c  = c0 + threadIdx.y + t;
        int hw = hw0 + threadIdx.x;
        if (hw < HW)
            tile[threadIdx.y + t][threadIdx.x] = src[(size_t)c * HW + hw];
    }
    __syncthreads();
    #pragma unroll
    for (int t = 0; t < 32; t += 8) {
        int hw = hw0 + threadIdx.y + t;
        int c  = c0 + threadIdx.x;
        if (hw < HW)
            dst[(size_t)hw * CH + c] = tile[threadIdx.x][threadIdx.y + t];
    }
}

// ---------------------------------------------------------------------------
// Kernel 2: build quad-corner layout from NHWC.
// One thread = one (b,h,w,c4) -> reads 4 float4 (coalesced), writes 4 float4
// (64B contiguous per thread, coalesced across c4).
// ---------------------------------------------------------------------------
__global__ void build_quad() {
    const int t = blockIdx.x * 256 + threadIdx.x;
    const int total = BATCH * QH * QW * (CH / 4);
    if (t >= total) return;

    const int c4 = t & 127;             // CH/4 = 128
    int r = t >> 7;
    const int w = r % QW;  r /= QW;
    const int h = r % QH;  r /= QH;
    const int b = r;

    const float* p = g_feat_hwc + ((size_t)b * HW + h * FW + w) * CH + c4 * 4;
    const float4 aa = *(const float4*)(p);
    const float4 bb = *(const float4*)(p + CH);
    const float4 cc = *(const float4*)(p + FW * CH);
    const float4 dd = *(const float4*)(p + FW * CH + CH);

    float4* o = g_quad + (((size_t)b * QH + h) * QW + w) * CH + c4 * 4;
    o[0] = make_float4(aa.x, bb.x, cc.x, dd.x);
    o[1] = make_float4(aa.y, bb.y, cc.y, dd.y);
    o[2] = make_float4(aa.z, bb.z, cc.z, dd.z);
    o[3] = make_float4(aa.w, bb.w, cc.w, dd.w);
}

// ---------------------------------------------------------------------------
// Kernel 3: one CTA per roi, 512 threads = one channel each.
// One LDG.128 per sample point (all 4 bilinear corners), fused 2x2 avg pool,
// smem-staged coalesced output.  R3 structure: independent unconditional-
// shaped loads, fully unrolled.
// ---------------------------------------------------------------------------
__global__ __launch_bounds__(CH, 2)
void roi_plus_avg_kernel(const float* __restrict__ rois,
                         float* __restrict__ out) {
    extern __shared__ float s_out[];   // OUT_PER_ROI floats

    const int n = blockIdx.x;
    const int c = threadIdx.x;

    __shared__ int   s_hs[PH], s_ws[PW];
    __shared__ float s_hr[PH], s_wr[PW];
    __shared__ int   s_hv[PH], s_wv[PW];
    __shared__ int   s_b;

    if (threadIdx.x < PH) {
        const int i = threadIdx.x;
        const float x1 = rois[n * 5 + 1] * SPATIAL_SCALE;
        const float y1 = rois[n * 5 + 2] * SPATIAL_SCALE;
        const float x2 = rois[n * 5 + 3] * SPATIAL_SCALE;
        const float y2 = rois[n * 5 + 4] * SPATIAL_SCALE;
        const float roi_w = fmaxf(x2 - x1 + 1.0f, 0.0f);
        const float roi_h = fmaxf(y2 - y1 + 1.0f, 0.0f);
        const float bin_h = roi_h * (1.0f / (PH - 1));
        const float bin_w = roi_w * (1.0f / (PW - 1));

        const float hh = y1 + (float)i * bin_h;
        const float ww = x1 + (float)i * bin_w;

        s_hv[i] = (hh >= 0.0f) && (hh < (float)FH);
        s_wv[i] = (ww >= 0.0f) && (ww < (float)FW);

        int hs = (int)floorf(hh);
        int ws = (int)floorf(ww);
        hs = min(max(hs, 0), FH - 2);
        ws = min(max(ws, 0), FW - 2);
        s_hs[i] = hs;
        s_ws[i] = ws;
        s_hr[i] = hh - (float)hs;
        s_wr[i] = ww - (float)ws;

        if (i == 0) s_b = (int)rois[n * 5 + 0];
    }
    __syncthreads();

    const float4* fq = g_quad + (size_t)s_b * QH * QW * CH + c;

    float prev[PW];
    float cur[PW];

    #pragma unroll
    for (int i = 0; i < PH; i++) {
        const int   hs = s_hs[i];
        const float hr = s_hr[i];
        const bool  hv = (s_hv[i] != 0);
        const float4* rowq = fq + (size_t)(hs * QW) * CH;

        #pragma unroll
        for (int j = 0; j < PW; j++) {
            float v = 0.0f;
            if (hv && s_wv[j]) {
                const float wr = s_wr[j];
                const float4 q = __ldg(rowq + (size_t)s_ws[j] * CH);
                const float top = fmaf(q.y - q.x, wr, q.x);
                const float bot = fmaf(q.w - q.z, wr, q.z);
                v = fmaf(bot - top, hr, top);
            }
            cur[j] = v;
        }

        if (i > 0) {
            float* o = s_out + c * 49 + (i - 1) * 7;   // stride 49 -> conflict-free
            #pragma unroll
            for (int j = 0; j < 7; j++)
                o[j] = 0.25f * (prev[j] + prev[j + 1] + cur[j] + cur[j + 1]);
        }
        #pragma unroll
        for (int j = 0; j < PW; j++) prev[j] = cur[j];
    }

    __syncthreads();

    // Cooperative fully-coalesced copy-out: 25088 floats = 6272 float4
    float4*       dst4 = (float4*)(out + (size_t)n * OUT_PER_ROI);
    const float4* src4 = (const float4*)s_out;
    #pragma unroll 4
    for (int idx = threadIdx.x; idx < OUT_PER_ROI / 4; idx += CH)
        dst4[idx] = src4[idx];
}

// ---------------------------------------------------------------------------
extern "C" void kernel_launch(void* const* d_in, const int* in_sizes, int n_in,
                              void* d_out, int out_size) {
    const float* features = (const float*)d_in[0];
    const float* rois     = (const float*)d_in[1];
    float*       out      = (float*)d_out;
    const int n_rois = in_sizes[1] / 5;

    cudaFuncSetAttribute(roi_plus_avg_kernel,
                         cudaFuncAttributeMaxDynamicSharedMemorySize,
                         SMEM_BYTES);

    dim3 tgrid((HW + 31) / 32, CH / 32, BATCH);
    dim3 tblk(32, 8);
    transpose_nchw_nhwc<<<tgrid, tblk>>>(features);

    const int qtotal  = BATCH * QH * QW * (CH / 4);
    build_quad<<<(qtotal + 255) / 256, 256>>>();

    roi_plus_avg_kernel<<<n_rois, CH, SMEM_BYTES>>>(rois, out);
}

// round 6
// speedup vs baseline: 1.9057x; 1.4996x over previous
#include <cuda_runtime.h>
#include <cuda_bf16.h>

#define BATCH 2
#define CH 512
#define FH 50
#define FW 75
#define HW (FH * FW)          // 3750
#define PH 8
#define PW 8
#define NTHREADS 256          // 2 channels per thread
#define OUT_PER_ROI (CH * 7 * 7)          // 25088 floats
#define SMEM_BYTES (OUT_PER_ROI * 4)      // 100352 bytes
#define SPATIAL_SCALE (1.0f / 16.0f)

// NHWC scratch: 2 * 3750 * 512 floats = 15.36 MB (fits L2)
__device__ float g_feat_hwc[BATCH * HW * CH];

// ---------------------------------------------------------------------------
// Kernel 1: NCHW -> NHWC transpose.
// ---------------------------------------------------------------------------
__global__ void transpose_nchw_nhwc(const float* __restrict__ in) {
    __shared__ float tile[32][33];
    const int b   = blockIdx.z;
    const int hw0 = blockIdx.x * 32;
    const int c0  = blockIdx.y * 32;

    const float* src = in + (size_t)b * CH * HW;
    float*       dst = g_feat_hwc + (size_t)b * HW * CH;

    #pragma unroll
    for (int t = 0; t < 32; t += 8) {
        int c  = c0 + threadIdx.y + t;
        int hw = hw0 + threadIdx.x;
        if (hw < HW)
            tile[threadIdx.y + t][threadIdx.x] = src[(size_t)c * HW + hw];
    }
    __syncthreads();
    #pragma unroll
    for (int t = 0; t < 32; t += 8) {
        int hw = hw0 + threadIdx.y + t;
        int c  = c0 + threadIdx.x;
        if (hw < HW)
            dst[(size_t)hw * CH + c] = tile[threadIdx.x][threadIdx.y + t];
    }
}

// ---------------------------------------------------------------------------
// Kernel 2: one CTA per roi, 256 threads = 2 consecutive channels each.
// float2 loads (LDG.64) on the NHWC array: same bytes/footprint/reuse as R3,
// half the LSU issue slots.  Fused 2x2 avg pool, smem-staged coalesced output.
// ---------------------------------------------------------------------------
__global__ __launch_bounds__(NTHREADS, 2)
void roi_plus_avg_kernel(const float* __restrict__ rois,
                         float* __restrict__ out) {
    extern __shared__ float s_out[];   // OUT_PER_ROI floats

    const int n  = blockIdx.x;
    const int c0 = threadIdx.x * 2;    // channels c0, c0+1

    __shared__ int   s_hs[PH], s_ws[PW];
    __shared__ float s_hr[PH], s_wr[PW];
    __shared__ int   s_hv[PH], s_wv[PW];
    __shared__ int   s_b;

    if (threadIdx.x < PH) {
        const int i = threadIdx.x;
        const float x1 = rois[n * 5 + 1] * SPATIAL_SCALE;
        const float y1 = rois[n * 5 + 2] * SPATIAL_SCALE;
        const float x2 = rois[n * 5 + 3] * SPATIAL_SCALE;
        const float y2 = rois[n * 5 + 4] * SPATIAL_SCALE;
        const float roi_w = fmaxf(x2 - x1 + 1.0f, 0.0f);
        const float roi_h = fmaxf(y2 - y1 + 1.0f, 0.0f);
        const float bin_h = roi_h * (1.0f / (PH - 1));
        const float bin_w = roi_w * (1.0f / (PW - 1));

        const float hh = y1 + (float)i * bin_h;
        const float ww = x1 + (float)i * bin_w;

        s_hv[i] = (hh >= 0.0f) && (hh < (float)FH);
        s_wv[i] = (ww >= 0.0f) && (ww < (float)FW);

        int hs = (int)floorf(hh);
        int ws = (int)floorf(ww);
        hs = min(max(hs, 0), FH - 2);
        ws = min(max(ws, 0), FW - 2);
        s_hs[i] = hs;
        s_ws[i] = ws;
        s_hr[i] = hh - (float)hs;
        s_wr[i] = ww - (float)ws;

        if (i == 0) s_b = (int)rois[n * 5 + 0];
    }
    __syncthreads();

    const float* fb = g_feat_hwc + (size_t)s_b * HW * CH + c0;

    float2 prev[PW];
    float2 cur[PW];

    #pragma unroll
    for (int i = 0; i < PH; i++) {
        const int   hs = s_hs[i];
        const float hr = s_hr[i];
        const bool  hv = (s_hv[i] != 0);
        const float* r0 = fb + (size_t)(hs * FW) * CH;
        const float* r1 = r0 + (size_t)FW * CH;

        #pragma unroll
        for (int j = 0; j < PW; j++) {
            float2 v = make_float2(0.0f, 0.0f);
            if (hv && s_wv[j]) {
                const int   ws = s_ws[j];
                const float wr = s_wr[j];
                const float2 ul = __ldg((const float2*)(r0 + (size_t)ws * CH));
                const float2 ur = __ldg((const float2*)(r0 + (size_t)(ws + 1) * CH));
                const float2 ll = __ldg((const float2*)(r1 + (size_t)ws * CH));
                const float2 lr = __ldg((const float2*)(r1 + (size_t)(ws + 1) * CH));
                const float tx = fmaf(ur.x - ul.x, wr, ul.x);
                const float bx = fmaf(lr.x - ll.x, wr, ll.x);
                const float ty = fmaf(ur.y - ul.y, wr, ul.y);
                const float by = fmaf(lr.y - ll.y, wr, ll.y);
                v.x = fmaf(bx - tx, hr, tx);
                v.y = fmaf(by - ty, hr, ty);
            }
            cur[j] = v;
        }

        if (i > 0) {
            // stage pooled row for both channels (stride 49 -> conflict-free)
            float* o0 = s_out + c0 * 49 + (i - 1) * 7;
            float* o1 = o0 + 49;
            #pragma unroll
            for (int j = 0; j < 7; j++) {
                o0[j] = 0.25f * (prev[j].x + prev[j + 1].x + cur[j].x + cur[j + 1].x);
                o1[j] = 0.25f * (prev[j].y + prev[j + 1].y + cur[j].y + cur[j + 1].y);
            }
        }
        #pragma unroll
        for (int j = 0; j < PW; j++) prev[j] = cur[j];
    }

    __syncthreads();

    // Cooperative fully-coalesced copy-out: 25088 floats = 6272 float4
    float4*       dst4 = (float4*)(out + (size_t)n * OUT_PER_ROI);
    const float4* src4 = (const float4*)s_out;
    #pragma unroll 4
    for (int idx = threadIdx.x; idx < OUT_PER_ROI / 4; idx += NTHREADS)
        dst4[idx] = src4[idx];
}

// ---------------------------------------------------------------------------
extern "C" void kernel_launch(void* const* d_in, const int* in_sizes, int n_in,
                              void* d_out, int out_size) {
    const float* features = (const float*)d_in[0];
    const float* rois     = (const float*)d_in[1];
    float*       out      = (float*)d_out;
    const int n_rois = in_sizes[1] / 5;

    cudaFuncSetAttribute(roi_plus_avg_kernel,
                         cudaFuncAttributeMaxDynamicSharedMemorySize,
                         SMEM_BYTES);

    dim3 tgrid((HW + 31) / 32, CH / 32, BATCH);
    dim3 tblk(32, 8);
    transpose_nchw_nhwc<<<tgrid, tblk>>>(features);

    roi_plus_avg_kernel<<<n_rois, NTHREADS, SMEM_BYTES>>>(rois, out);
}